// round 2
// baseline (speedup 1.0000x reference)
#include <cuda_runtime.h>
#include <math.h>

#define LSEQ   1024
#define DMODEL 1024
#define NHEADS 16
#define DHEAD  64
#define NBATCH 8
#define NROWS  (NBATCH * LSEQ)   // 8192

// Scratch (allocation-free rule: __device__ globals)
static __device__ float g_Q[NROWS * DMODEL];
static __device__ float g_K[NROWS * DMODEL];
static __device__ float g_V[NROWS * DMODEL];
static __device__ float g_CTX[NROWS * DMODEL];
static __device__ float g_Y[NROWS * DMODEL];
static __device__ float g_S[(size_t)NBATCH * NHEADS * LSEQ * LSEQ]; // 536 MB attn scratch

// ---------------------------------------------------------------------------
// Generic NN SGEMM: C[M,N] = A[M,K] @ B[K,N] (+ R), N = 1024, BM=BN=128, BK=16
// grid = (N/128, M/128), 256 threads, 8x8 per-thread microtile.
// ---------------------------------------------------------------------------
__global__ __launch_bounds__(256) void sgemm_nn_kernel(
    const float* __restrict__ A, const float* __restrict__ B,
    float* __restrict__ C, const float* __restrict__ R, int K)
{
    const int N = DMODEL;
    __shared__ float As[16][128];
    __shared__ float Bs[16][128];
    const int tid = threadIdx.x;
    const int bm = blockIdx.y * 128, bn = blockIdx.x * 128;
    const int m0 = (tid >> 4) * 8, n0 = (tid & 15) * 8;
    float acc[8][8] = {};
    for (int k0 = 0; k0 < K; k0 += 16) {
        #pragma unroll
        for (int t = 0; t < 2; t++) {
            int id = tid + t * 256;
            int r = id >> 2, c = (id & 3) << 2;
            float4 v = *(const float4*)(A + (size_t)(bm + r) * K + k0 + c);
            As[c][r] = v.x; As[c + 1][r] = v.y; As[c + 2][r] = v.z; As[c + 3][r] = v.w;
        }
        #pragma unroll
        for (int t = 0; t < 2; t++) {
            int id = tid + t * 256;
            int r = id >> 5, c = (id & 31) << 2;
            *(float4*)(&Bs[r][c]) = *(const float4*)(B + (size_t)(k0 + r) * N + bn + c);
        }
        __syncthreads();
        #pragma unroll
        for (int kk = 0; kk < 16; kk++) {
            float a[8], b[8];
            *(float4*)(a)     = *(float4*)(&As[kk][m0]);
            *(float4*)(a + 4) = *(float4*)(&As[kk][m0 + 4]);
            *(float4*)(b)     = *(float4*)(&Bs[kk][n0]);
            *(float4*)(b + 4) = *(float4*)(&Bs[kk][n0 + 4]);
            #pragma unroll
            for (int i = 0; i < 8; i++)
                #pragma unroll
                for (int j = 0; j < 8; j++)
                    acc[i][j] += a[i] * b[j];
        }
        __syncthreads();
    }
    #pragma unroll
    for (int i = 0; i < 8; i++) {
        size_t row = (size_t)(bm + m0 + i) * N + bn + n0;
        #pragma unroll
        for (int j = 0; j < 8; j += 4) {
            float4 v = make_float4(acc[i][j], acc[i][j + 1], acc[i][j + 2], acc[i][j + 3]);
            if (R) {
                float4 r4 = *(const float4*)(R + row + j);
                v.x += r4.x; v.y += r4.y; v.z += r4.z; v.w += r4.w;
            }
            *(float4*)(C + row + j) = v;
        }
    }
}

// ---------------------------------------------------------------------------
// Scores: per (b,h): S = scale * Q @ K^T, masked.  NT GEMM, Kdim=64.
// grid = (8, 8, 128), 256 threads.
// mask read as 32-bit words: nonzero == masked (works for int32 and fp32 bool).
// ---------------------------------------------------------------------------
__global__ __launch_bounds__(256) void scores_kernel(
    const float* __restrict__ Qg, const float* __restrict__ Kg,
    float* __restrict__ S, const unsigned int* __restrict__ mask)
{
    const int z = blockIdx.z, b = z >> 4, h = z & 15;
    const float* A  = Qg + (size_t)b * LSEQ * DMODEL + h * DHEAD;
    const float* Bp = Kg + (size_t)b * LSEQ * DMODEL + h * DHEAD;
    float* C = S + (size_t)z * LSEQ * LSEQ;
    const unsigned int* mb = mask + (size_t)b * LSEQ * LSEQ;
    __shared__ float As[16][128];
    __shared__ float Bs[16][128];
    const int tid = threadIdx.x;
    const int bm = blockIdx.y * 128, bn = blockIdx.x * 128;
    const int m0 = (tid >> 4) * 8, n0 = (tid & 15) * 8;
    float acc[8][8] = {};
    for (int k0 = 0; k0 < DHEAD; k0 += 16) {
        #pragma unroll
        for (int t = 0; t < 2; t++) {
            int id = tid + t * 256;
            int r = id >> 2, c = (id & 3) << 2;
            float4 v = *(const float4*)(A + (size_t)(bm + r) * DMODEL + k0 + c);
            As[c][r] = v.x; As[c + 1][r] = v.y; As[c + 2][r] = v.z; As[c + 3][r] = v.w;
            float4 w = *(const float4*)(Bp + (size_t)(bn + r) * DMODEL + k0 + c);
            Bs[c][r] = w.x; Bs[c + 1][r] = w.y; Bs[c + 2][r] = w.z; Bs[c + 3][r] = w.w;
        }
        __syncthreads();
        #pragma unroll
        for (int kk = 0; kk < 16; kk++) {
            float a[8], bb[8];
            *(float4*)(a)      = *(float4*)(&As[kk][m0]);
            *(float4*)(a + 4)  = *(float4*)(&As[kk][m0 + 4]);
            *(float4*)(bb)     = *(float4*)(&Bs[kk][n0]);
            *(float4*)(bb + 4) = *(float4*)(&Bs[kk][n0 + 4]);
            #pragma unroll
            for (int i = 0; i < 8; i++)
                #pragma unroll
                for (int j = 0; j < 8; j++)
                    acc[i][j] += a[i] * bb[j];
        }
        __syncthreads();
    }
    const float scale = 0.125f;  // 1/sqrt(64)
    #pragma unroll
    for (int i = 0; i < 8; i++) {
        const int q = bm + m0 + i;
        #pragma unroll
        for (int j = 0; j < 8; j++) {
            const int kc = bn + n0 + j;
            float s = acc[i][j] * scale;
            if (mb[(size_t)q * LSEQ + kc] != 0u) s = -1e9f;
            C[(size_t)q * LSEQ + kc] = s;
        }
    }
}

// ---------------------------------------------------------------------------
// Row softmax over 1024 elements, in place. grid = 131072 rows, 256 threads.
// ---------------------------------------------------------------------------
__global__ __launch_bounds__(256) void softmax_kernel(float* __restrict__ S)
{
    __shared__ float red[256];
    float* p = S + (size_t)blockIdx.x * LSEQ;
    const int tid = threadIdx.x;
    float4 v = *(float4*)(p + tid * 4);
    red[tid] = fmaxf(fmaxf(v.x, v.y), fmaxf(v.z, v.w));
    __syncthreads();
    for (int s = 128; s > 0; s >>= 1) {
        if (tid < s) red[tid] = fmaxf(red[tid], red[tid + s]);
        __syncthreads();
    }
    const float mx = red[0];
    __syncthreads();
    v.x = __expf(v.x - mx); v.y = __expf(v.y - mx);
    v.z = __expf(v.z - mx); v.w = __expf(v.w - mx);
    red[tid] = v.x + v.y + v.z + v.w;
    __syncthreads();
    for (int s = 128; s > 0; s >>= 1) {
        if (tid < s) red[tid] += red[tid + s];
        __syncthreads();
    }
    const float inv = 1.0f / red[0];
    v.x *= inv; v.y *= inv; v.z *= inv; v.w *= inv;
    *(float4*)(p + tid * 4) = v;
}

// ---------------------------------------------------------------------------
// Context: per (b,h): CTX = attn[1024,1024] @ V[1024,64], written into
// [B, L, H*64] layout. grid = (1, 8, 128), BM=128, BN=64, BK=16.
// ---------------------------------------------------------------------------
__global__ __launch_bounds__(256) void av_kernel(
    const float* __restrict__ S, const float* __restrict__ Vg, float* __restrict__ CTX)
{
    const int z = blockIdx.z, b = z >> 4, h = z & 15;
    const float* A  = S + (size_t)z * LSEQ * LSEQ;
    const float* Bp = Vg + (size_t)b * LSEQ * DMODEL + h * DHEAD;
    float* C = CTX + (size_t)b * LSEQ * DMODEL + h * DHEAD;
    __shared__ float As[16][128];
    __shared__ float Bs[16][64];
    const int tid = threadIdx.x;
    const int bm = blockIdx.y * 128;
    const int m0 = (tid >> 4) * 8, n0 = (tid & 15) * 4;
    float acc[8][4] = {};
    for (int k0 = 0; k0 < LSEQ; k0 += 16) {
        #pragma unroll
        for (int t = 0; t < 2; t++) {
            int id = tid + t * 256;
            int r = id >> 2, c = (id & 3) << 2;
            float4 v = *(const float4*)(A + (size_t)(bm + r) * LSEQ + k0 + c);
            As[c][r] = v.x; As[c + 1][r] = v.y; As[c + 2][r] = v.z; As[c + 3][r] = v.w;
        }
        {
            int r = tid >> 4, c = (tid & 15) << 2;
            *(float4*)(&Bs[r][c]) = *(const float4*)(Bp + (size_t)(k0 + r) * DMODEL + c);
        }
        __syncthreads();
        #pragma unroll
        for (int kk = 0; kk < 16; kk++) {
            float a[8], b4[4];
            *(float4*)(a)     = *(float4*)(&As[kk][m0]);
            *(float4*)(a + 4) = *(float4*)(&As[kk][m0 + 4]);
            *(float4*)(b4)    = *(float4*)(&Bs[kk][n0]);
            #pragma unroll
            for (int i = 0; i < 8; i++)
                #pragma unroll
                for (int j = 0; j < 4; j++)
                    acc[i][j] += a[i] * b4[j];
        }
        __syncthreads();
    }
    #pragma unroll
    for (int i = 0; i < 8; i++) {
        float4 v = make_float4(acc[i][0], acc[i][1], acc[i][2], acc[i][3]);
        *(float4*)(C + (size_t)(bm + m0 + i) * DMODEL + n0) = v;
    }
}

// ---------------------------------------------------------------------------
// Row LayerNorm over 1024 (residual already added upstream). grid = 8192 rows.
// ---------------------------------------------------------------------------
__global__ __launch_bounds__(256) void ln_kernel(
    const float* __restrict__ Y, float* __restrict__ O,
    const float* __restrict__ gamma, const float* __restrict__ beta)
{
    __shared__ float red[256];
    const float* p = Y + (size_t)blockIdx.x * DMODEL;
    const int tid = threadIdx.x;
    float4 v = *(const float4*)(p + tid * 4);
    red[tid] = v.x + v.y + v.z + v.w;
    __syncthreads();
    for (int s = 128; s > 0; s >>= 1) {
        if (tid < s) red[tid] += red[tid + s];
        __syncthreads();
    }
    const float mu = red[0] * (1.0f / DMODEL);
    __syncthreads();
    const float dx = v.x - mu, dy = v.y - mu, dz = v.z - mu, dw = v.w - mu;
    red[tid] = dx * dx + dy * dy + dz * dz + dw * dw;
    __syncthreads();
    for (int s = 128; s > 0; s >>= 1) {
        if (tid < s) red[tid] += red[tid + s];
        __syncthreads();
    }
    const float rstd = rsqrtf(red[0] * (1.0f / DMODEL) + 1e-6f);
    const float4 g  = *(const float4*)(gamma + tid * 4);
    const float4 be = *(const float4*)(beta + tid * 4);
    float4 o;
    o.x = dx * rstd * g.x + be.x;
    o.y = dy * rstd * g.y + be.y;
    o.z = dz * rstd * g.z + be.z;
    o.w = dw * rstd * g.w + be.w;
    *(float4*)(O + (size_t)blockIdx.x * DMODEL + tid * 4) = o;
}

// ---------------------------------------------------------------------------
extern "C" void kernel_launch(void* const* d_in, const int* in_sizes, int n_in,
                              void* d_out, int out_size)
{
    const float* X    = (const float*)d_in[0];
    const unsigned int* mask = (const unsigned int*)d_in[1];  // bool -> 4-byte (int32/fp32): nonzero == masked
    const float* W_Q  = (const float*)d_in[2];
    const float* W_K  = (const float*)d_in[3];
    const float* W_V  = (const float*)d_in[4];
    const float* W_O  = (const float*)d_in[5];
    const float* gamma = (const float*)d_in[6];
    const float* beta  = (const float*)d_in[7];

    float *Qp, *Kp, *Vp, *Cp, *Yp, *Sp;
    cudaGetSymbolAddress((void**)&Qp, g_Q);
    cudaGetSymbolAddress((void**)&Kp, g_K);
    cudaGetSymbolAddress((void**)&Vp, g_V);
    cudaGetSymbolAddress((void**)&Cp, g_CTX);
    cudaGetSymbolAddress((void**)&Yp, g_Y);
    cudaGetSymbolAddress((void**)&Sp, g_S);

    const size_t LN_ELEMS   = (size_t)NROWS * DMODEL;                     // 8388608
    const size_t ATTN_ELEMS = (size_t)NBATCH * NHEADS * LSEQ * LSEQ;      // 134217728

    float* out_ln;
    float* attn_dst;
    if ((size_t)out_size >= LN_ELEMS + ATTN_ELEMS) {
        out_ln = (float*)d_out;                 // (ln_out, attn) concatenated, ln first
        attn_dst = (float*)d_out + LN_ELEMS;
    } else if ((size_t)out_size == ATTN_ELEMS) {
        attn_dst = (float*)d_out;               // attn-only output
        out_ln = Yp;                            // LN to scratch
    } else {
        out_ln = (float*)d_out;                 // ln-only output
        attn_dst = Sp;
    }

    dim3 thr(256);
    sgemm_nn_kernel<<<dim3(8, 64), thr>>>(X, W_Q, Qp, nullptr, DMODEL);
    sgemm_nn_kernel<<<dim3(8, 64), thr>>>(X, W_K, Kp, nullptr, DMODEL);
    sgemm_nn_kernel<<<dim3(8, 64), thr>>>(X, W_V, Vp, nullptr, DMODEL);
    scores_kernel<<<dim3(8, 8, NBATCH * NHEADS), thr>>>(Qp, Kp, attn_dst, mask);
    softmax_kernel<<<dim3(NBATCH * NHEADS * LSEQ), thr>>>(attn_dst);
    av_kernel<<<dim3(1, 8, NBATCH * NHEADS), thr>>>(attn_dst, Vp, Cp);
    sgemm_nn_kernel<<<dim3(8, 64), thr>>>(Cp, W_O, Yp, X, DMODEL);
    ln_kernel<<<dim3(NROWS), thr>>>(Yp, out_ln, gamma, beta);
}

// round 3
// speedup vs baseline: 1.7432x; 1.7432x over previous
#include <cuda_runtime.h>
#include <math.h>

#define LSEQ   1024
#define DMODEL 1024
#define NHEADS 16
#define DHEAD  64
#define NBATCH 8
#define NROWS  (NBATCH * LSEQ)   // 8192

// Scratch (allocation-free rule: __device__ globals)
static __device__ float g_Q[NROWS * DMODEL];
static __device__ float g_K[NROWS * DMODEL];
static __device__ float g_V[NROWS * DMODEL];
static __device__ float g_CTX[NROWS * DMODEL];
static __device__ float g_Y[NROWS * DMODEL];
static __device__ float g_S[(size_t)NBATCH * NHEADS * LSEQ * LSEQ]; // 536 MB attn scratch

// ---------------------------------------------------------------------------
// tf32 helpers
// ---------------------------------------------------------------------------
__device__ __forceinline__ void tf32_split(float x, float& hi, float& lo) {
    unsigned h;
    asm("cvt.rna.tf32.f32 %0, %1;" : "=r"(h) : "f"(x));
    hi = __uint_as_float(h);
    float r = x - hi;
    unsigned l;
    asm("cvt.rna.tf32.f32 %0, %1;" : "=r"(l) : "f"(r));
    lo = __uint_as_float(l);
}

__device__ __forceinline__ void mma8(float* c, const unsigned* a, const unsigned* b) {
    asm volatile(
        "mma.sync.aligned.m16n8k8.row.col.f32.tf32.tf32.f32 "
        "{%0,%1,%2,%3}, {%4,%5,%6,%7}, {%8,%9}, {%0,%1,%2,%3};"
        : "+f"(c[0]), "+f"(c[1]), "+f"(c[2]), "+f"(c[3])
        : "r"(a[0]), "r"(a[1]), "r"(a[2]), "r"(a[3]), "r"(b[0]), "r"(b[1]));
}

#define PAD_A 136   // 128 + 8: (136*tig + gid) % 32 -> 8*tig+gid, all 32 lanes distinct banks
#define PAD_B 72    // 64 + 8  for av-kernel V tile

// ---------------------------------------------------------------------------
// Dense NN GEMM: C[M,1024] = A[M,K] @ B[K,1024] (+R).  3xTF32 warp MMA.
// BM=BN=128, BK=16. 256 thr = 8 warps, warp tile 64x32 (mf=4, nf=4).
// grid = (N/128, M/128).
// ---------------------------------------------------------------------------
__global__ __launch_bounds__(256) void mma_nn_kernel(
    const float* __restrict__ A, const float* __restrict__ B,
    float* __restrict__ C, const float* __restrict__ R, int K)
{
    const int N = DMODEL;
    __shared__ float AsH[16][PAD_A], AsL[16][PAD_A];
    __shared__ float BsH[16][PAD_A], BsL[16][PAD_A];

    const int tid = threadIdx.x;
    const int wid = tid >> 5, lane = tid & 31;
    const int gid = lane >> 2, tig = lane & 3;
    const int wm = (wid & 1) * 64, wn = (wid >> 1) * 32;
    const int bm = blockIdx.y * 128, bn = blockIdx.x * 128;

    float acc[4][4][4] = {};

    for (int k0 = 0; k0 < K; k0 += 16) {
        // A tile 128x16 -> transposed [k][m], split hi/lo
        #pragma unroll
        for (int t = 0; t < 2; t++) {
            int id = tid + t * 256;
            int r = id >> 2, c = (id & 3) << 2;
            float4 v = *(const float4*)(A + (size_t)(bm + r) * K + k0 + c);
            float h, l;
            tf32_split(v.x, h, l); AsH[c    ][r] = h; AsL[c    ][r] = l;
            tf32_split(v.y, h, l); AsH[c + 1][r] = h; AsL[c + 1][r] = l;
            tf32_split(v.z, h, l); AsH[c + 2][r] = h; AsL[c + 2][r] = l;
            tf32_split(v.w, h, l); AsH[c + 3][r] = h; AsL[c + 3][r] = l;
        }
        // B tile 16x128 -> [k][n], split hi/lo
        #pragma unroll
        for (int t = 0; t < 2; t++) {
            int id = tid + t * 256;
            int r = id >> 5, c = (id & 31) << 2;
            float4 v = *(const float4*)(B + (size_t)(k0 + r) * N + bn + c);
            float4 h4, l4;
            tf32_split(v.x, h4.x, l4.x);
            tf32_split(v.y, h4.y, l4.y);
            tf32_split(v.z, h4.z, l4.z);
            tf32_split(v.w, h4.w, l4.w);
            *(float4*)(&BsH[r][c]) = h4;
            *(float4*)(&BsL[r][c]) = l4;
        }
        __syncthreads();

        #pragma unroll
        for (int ks = 0; ks < 16; ks += 8) {
            unsigned aH[4][4], aL[4][4], bH[4][2], bL[4][2];
            #pragma unroll
            for (int mf = 0; mf < 4; mf++) {
                int m = wm + mf * 16 + gid;
                aH[mf][0] = __float_as_uint(AsH[ks + tig    ][m    ]);
                aH[mf][1] = __float_as_uint(AsH[ks + tig    ][m + 8]);
                aH[mf][2] = __float_as_uint(AsH[ks + tig + 4][m    ]);
                aH[mf][3] = __float_as_uint(AsH[ks + tig + 4][m + 8]);
                aL[mf][0] = __float_as_uint(AsL[ks + tig    ][m    ]);
                aL[mf][1] = __float_as_uint(AsL[ks + tig    ][m + 8]);
                aL[mf][2] = __float_as_uint(AsL[ks + tig + 4][m    ]);
                aL[mf][3] = __float_as_uint(AsL[ks + tig + 4][m + 8]);
            }
            #pragma unroll
            for (int nf = 0; nf < 4; nf++) {
                int n = wn + nf * 8 + gid;
                bH[nf][0] = __float_as_uint(BsH[ks + tig    ][n]);
                bH[nf][1] = __float_as_uint(BsH[ks + tig + 4][n]);
                bL[nf][0] = __float_as_uint(BsL[ks + tig    ][n]);
                bL[nf][1] = __float_as_uint(BsL[ks + tig + 4][n]);
            }
            #pragma unroll
            for (int mf = 0; mf < 4; mf++)
                #pragma unroll
                for (int nf = 0; nf < 4; nf++) {
                    mma8(acc[mf][nf], aH[mf], bH[nf]);
                    mma8(acc[mf][nf], aH[mf], bL[nf]);
                    mma8(acc[mf][nf], aL[mf], bH[nf]);
                }
        }
        __syncthreads();
    }

    #pragma unroll
    for (int mf = 0; mf < 4; mf++) {
        #pragma unroll
        for (int nf = 0; nf < 4; nf++) {
            int m = bm + wm + mf * 16 + gid;
            int n = bn + wn + nf * 8 + 2 * tig;
            float2 v0 = make_float2(acc[mf][nf][0], acc[mf][nf][1]);
            float2 v1 = make_float2(acc[mf][nf][2], acc[mf][nf][3]);
            if (R) {
                float2 r0 = *(const float2*)(R + (size_t)m * N + n);
                float2 r1 = *(const float2*)(R + (size_t)(m + 8) * N + n);
                v0.x += r0.x; v0.y += r0.y; v1.x += r1.x; v1.y += r1.y;
            }
            *(float2*)(C + (size_t)m * N + n) = v0;
            *(float2*)(C + (size_t)(m + 8) * N + n) = v1;
        }
    }
}

// ---------------------------------------------------------------------------
// Scores: per (b,h): S = 0.125 * Q @ K^T, masked. 3xTF32.
// BM=BN=128, K=64. grid = (8, 8, 128).
// ---------------------------------------------------------------------------
__global__ __launch_bounds__(256) void mma_scores_kernel(
    const float* __restrict__ Qg, const float* __restrict__ Kg,
    float* __restrict__ S, const unsigned int* __restrict__ mask)
{
    const int z = blockIdx.z, b = z >> 4, h = z & 15;
    const float* Aq = Qg + (size_t)b * LSEQ * DMODEL + h * DHEAD;
    const float* Bk = Kg + (size_t)b * LSEQ * DMODEL + h * DHEAD;
    float* C = S + (size_t)z * LSEQ * LSEQ;
    const unsigned int* mb = mask + (size_t)b * LSEQ * LSEQ;

    __shared__ float AsH[16][PAD_A], AsL[16][PAD_A];
    __shared__ float BsH[16][PAD_A], BsL[16][PAD_A];

    const int tid = threadIdx.x;
    const int wid = tid >> 5, lane = tid & 31;
    const int gid = lane >> 2, tig = lane & 3;
    const int wm = (wid & 1) * 64, wn = (wid >> 1) * 32;
    const int bm = blockIdx.y * 128, bn = blockIdx.x * 128;

    float acc[4][4][4] = {};

    for (int k0 = 0; k0 < DHEAD; k0 += 16) {
        // Q tile 128x16 transposed; K tile 128x16 transposed (col-major B)
        #pragma unroll
        for (int t = 0; t < 2; t++) {
            int id = tid + t * 256;
            int r = id >> 2, c = (id & 3) << 2;
            float4 v = *(const float4*)(Aq + (size_t)(bm + r) * DMODEL + k0 + c);
            float h, l;
            tf32_split(v.x, h, l); AsH[c    ][r] = h; AsL[c    ][r] = l;
            tf32_split(v.y, h, l); AsH[c + 1][r] = h; AsL[c + 1][r] = l;
            tf32_split(v.z, h, l); AsH[c + 2][r] = h; AsL[c + 2][r] = l;
            tf32_split(v.w, h, l); AsH[c + 3][r] = h; AsL[c + 3][r] = l;
            float4 w = *(const float4*)(Bk + (size_t)(bn + r) * DMODEL + k0 + c);
            tf32_split(w.x, h, l); BsH[c    ][r] = h; BsL[c    ][r] = l;
            tf32_split(w.y, h, l); BsH[c + 1][r] = h; BsL[c + 1][r] = l;
            tf32_split(w.z, h, l); BsH[c + 2][r] = h; BsL[c + 2][r] = l;
            tf32_split(w.w, h, l); BsH[c + 3][r] = h; BsL[c + 3][r] = l;
        }
        __syncthreads();

        #pragma unroll
        for (int ks = 0; ks < 16; ks += 8) {
            unsigned aH[4][4], aL[4][4], bH[4][2], bL[4][2];
            #pragma unroll
            for (int mf = 0; mf < 4; mf++) {
                int m = wm + mf * 16 + gid;
                aH[mf][0] = __float_as_uint(AsH[ks + tig    ][m    ]);
                aH[mf][1] = __float_as_uint(AsH[ks + tig    ][m + 8]);
                aH[mf][2] = __float_as_uint(AsH[ks + tig + 4][m    ]);
                aH[mf][3] = __float_as_uint(AsH[ks + tig + 4][m + 8]);
                aL[mf][0] = __float_as_uint(AsL[ks + tig    ][m    ]);
                aL[mf][1] = __float_as_uint(AsL[ks + tig    ][m + 8]);
                aL[mf][2] = __float_as_uint(AsL[ks + tig + 4][m    ]);
                aL[mf][3] = __float_as_uint(AsL[ks + tig + 4][m + 8]);
            }
            #pragma unroll
            for (int nf = 0; nf < 4; nf++) {
                int n = wn + nf * 8 + gid;
                bH[nf][0] = __float_as_uint(BsH[ks + tig    ][n]);
                bH[nf][1] = __float_as_uint(BsH[ks + tig + 4][n]);
                bL[nf][0] = __float_as_uint(BsL[ks + tig    ][n]);
                bL[nf][1] = __float_as_uint(BsL[ks + tig + 4][n]);
            }
            #pragma unroll
            for (int mf = 0; mf < 4; mf++)
                #pragma unroll
                for (int nf = 0; nf < 4; nf++) {
                    mma8(acc[mf][nf], aH[mf], bH[nf]);
                    mma8(acc[mf][nf], aH[mf], bL[nf]);
                    mma8(acc[mf][nf], aL[mf], bH[nf]);
                }
        }
        __syncthreads();
    }

    const float scale = 0.125f;
    #pragma unroll
    for (int mf = 0; mf < 4; mf++) {
        #pragma unroll
        for (int nf = 0; nf < 4; nf++) {
            int m = bm + wm + mf * 16 + gid;
            int n = bn + wn + nf * 8 + 2 * tig;
            #pragma unroll
            for (int half = 0; half < 2; half++) {
                int q = m + half * 8;
                float s0 = acc[mf][nf][half * 2]     * scale;
                float s1 = acc[mf][nf][half * 2 + 1] * scale;
                if (mb[(size_t)q * LSEQ + n]     != 0u) s0 = -1e9f;
                if (mb[(size_t)q * LSEQ + n + 1] != 0u) s1 = -1e9f;
                *(float2*)(C + (size_t)q * LSEQ + n) = make_float2(s0, s1);
            }
        }
    }
}

// ---------------------------------------------------------------------------
// Row softmax over 1024 elements, in place. grid = 131072 rows.
// ---------------------------------------------------------------------------
__global__ __launch_bounds__(256) void softmax_kernel(float* __restrict__ S)
{
    __shared__ float red[256];
    float* p = S + (size_t)blockIdx.x * LSEQ;
    const int tid = threadIdx.x;
    float4 v = *(float4*)(p + tid * 4);
    red[tid] = fmaxf(fmaxf(v.x, v.y), fmaxf(v.z, v.w));
    __syncthreads();
    for (int s = 128; s > 0; s >>= 1) {
        if (tid < s) red[tid] = fmaxf(red[tid], red[tid + s]);
        __syncthreads();
    }
    const float mx = red[0];
    __syncthreads();
    v.x = __expf(v.x - mx); v.y = __expf(v.y - mx);
    v.z = __expf(v.z - mx); v.w = __expf(v.w - mx);
    red[tid] = v.x + v.y + v.z + v.w;
    __syncthreads();
    for (int s = 128; s > 0; s >>= 1) {
        if (tid < s) red[tid] += red[tid + s];
        __syncthreads();
    }
    const float inv = 1.0f / red[0];
    v.x *= inv; v.y *= inv; v.z *= inv; v.w *= inv;
    *(float4*)(p + tid * 4) = v;
}

// ---------------------------------------------------------------------------
// Context: per (b,h): CTX = attn[1024,1024] @ V[1024,64].  3xTF32.
// BM=128, BN=64, BK=16. 8 warps, warp tile 64x16 (mf=4, nf=2).
// grid = (1, 8, 128).
// ---------------------------------------------------------------------------
__global__ __launch_bounds__(256) void mma_av_kernel(
    const float* __restrict__ S, const float* __restrict__ Vg, float* __restrict__ CTX)
{
    const int z = blockIdx.z, b = z >> 4, h = z & 15;
    const float* A  = S + (size_t)z * LSEQ * LSEQ;
    const float* Bp = Vg + (size_t)b * LSEQ * DMODEL + h * DHEAD;
    float* C = CTX + (size_t)b * LSEQ * DMODEL + h * DHEAD;

    __shared__ float AsH[16][PAD_A], AsL[16][PAD_A];
    __shared__ float BsH[16][PAD_B], BsL[16][PAD_B];

    const int tid = threadIdx.x;
    const int wid = tid >> 5, lane = tid & 31;
    const int gid = lane >> 2, tig = lane & 3;
    const int wm = (wid & 1) * 64, wn = (wid >> 1) * 16;
    const int bm = blockIdx.y * 128;

    float acc[4][2][4] = {};

    for (int k0 = 0; k0 < LSEQ; k0 += 16) {
        #pragma unroll
        for (int t = 0; t < 2; t++) {
            int id = tid + t * 256;
            int r = id >> 2, c = (id & 3) << 2;
            float4 v = *(const float4*)(A + (size_t)(bm + r) * LSEQ + k0 + c);
            float hh, ll;
            tf32_split(v.x, hh, ll); AsH[c    ][r] = hh; AsL[c    ][r] = ll;
            tf32_split(v.y, hh, ll); AsH[c + 1][r] = hh; AsL[c + 1][r] = ll;
            tf32_split(v.z, hh, ll); AsH[c + 2][r] = hh; AsL[c + 2][r] = ll;
            tf32_split(v.w, hh, ll); AsH[c + 3][r] = hh; AsL[c + 3][r] = ll;
        }
        {
            int r = tid >> 4, c = (tid & 15) << 2;
            float4 v = *(const float4*)(Bp + (size_t)(k0 + r) * DMODEL + c);
            float4 h4, l4;
            tf32_split(v.x, h4.x, l4.x);
            tf32_split(v.y, h4.y, l4.y);
            tf32_split(v.z, h4.z, l4.z);
            tf32_split(v.w, h4.w, l4.w);
            *(float4*)(&BsH[r][c]) = h4;
            *(float4*)(&BsL[r][c]) = l4;
        }
        __syncthreads();

        #pragma unroll
        for (int ks = 0; ks < 16; ks += 8) {
            unsigned aH[4][4], aL[4][4], bH[2][2], bL[2][2];
            #pragma unroll
            for (int mf = 0; mf < 4; mf++) {
                int m = wm + mf * 16 + gid;
                aH[mf][0] = __float_as_uint(AsH[ks + tig    ][m    ]);
                aH[mf][1] = __float_as_uint(AsH[ks + tig    ][m + 8]);
                aH[mf][2] = __float_as_uint(AsH[ks + tig + 4][m    ]);
                aH[mf][3] = __float_as_uint(AsH[ks + tig + 4][m + 8]);
                aL[mf][0] = __float_as_uint(AsL[ks + tig    ][m    ]);
                aL[mf][1] = __float_as_uint(AsL[ks + tig    ][m + 8]);
                aL[mf][2] = __float_as_uint(AsL[ks + tig + 4][m    ]);
                aL[mf][3] = __float_as_uint(AsL[ks + tig + 4][m + 8]);
            }
            #pragma unroll
            for (int nf = 0; nf < 2; nf++) {
                int n = wn + nf * 8 + gid;
                bH[nf][0] = __float_as_uint(BsH[ks + tig    ][n]);
                bH[nf][1] = __float_as_uint(BsH[ks + tig + 4][n]);
                bL[nf][0] = __float_as_uint(BsL[ks + tig    ][n]);
                bL[nf][1] = __float_as_uint(BsL[ks + tig + 4][n]);
            }
            #pragma unroll
            for (int mf = 0; mf < 4; mf++)
                #pragma unroll
                for (int nf = 0; nf < 2; nf++) {
                    mma8(acc[mf][nf], aH[mf], bH[nf]);
                    mma8(acc[mf][nf], aH[mf], bL[nf]);
                    mma8(acc[mf][nf], aL[mf], bH[nf]);
                }
        }
        __syncthreads();
    }

    #pragma unroll
    for (int mf = 0; mf < 4; mf++) {
        #pragma unroll
        for (int nf = 0; nf < 2; nf++) {
            int m = bm + wm + mf * 16 + gid;
            int n = wn + nf * 8 + 2 * tig;
            *(float2*)(C + (size_t)m * DMODEL + n) =
                make_float2(acc[mf][nf][0], acc[mf][nf][1]);
            *(float2*)(C + (size_t)(m + 8) * DMODEL + n) =
                make_float2(acc[mf][nf][2], acc[mf][nf][3]);
        }
    }
}

// ---------------------------------------------------------------------------
// Row LayerNorm over 1024. grid = 8192 rows.
// ---------------------------------------------------------------------------
__global__ __launch_bounds__(256) void ln_kernel(
    const float* __restrict__ Y, float* __restrict__ O,
    const float* __restrict__ gamma, const float* __restrict__ beta)
{
    __shared__ float red[256];
    const float* p = Y + (size_t)blockIdx.x * DMODEL;
    const int tid = threadIdx.x;
    float4 v = *(const float4*)(p + tid * 4);
    red[tid] = v.x + v.y + v.z + v.w;
    __syncthreads();
    for (int s = 128; s > 0; s >>= 1) {
        if (tid < s) red[tid] += red[tid + s];
        __syncthreads();
    }
    const float mu = red[0] * (1.0f / DMODEL);
    __syncthreads();
    const float dx = v.x - mu, dy = v.y - mu, dz = v.z - mu, dw = v.w - mu;
    red[tid] = dx * dx + dy * dy + dz * dz + dw * dw;
    __syncthreads();
    for (int s = 128; s > 0; s >>= 1) {
        if (tid < s) red[tid] += red[tid + s];
        __syncthreads();
    }
    const float rstd = rsqrtf(red[0] * (1.0f / DMODEL) + 1e-6f);
    const float4 g  = *(const float4*)(gamma + tid * 4);
    const float4 be = *(const float4*)(beta + tid * 4);
    float4 o;
    o.x = dx * rstd * g.x + be.x;
    o.y = dy * rstd * g.y + be.y;
    o.z = dz * rstd * g.z + be.z;
    o.w = dw * rstd * g.w + be.w;
    *(float4*)(O + (size_t)blockIdx.x * DMODEL + tid * 4) = o;
}

// ---------------------------------------------------------------------------
extern "C" void kernel_launch(void* const* d_in, const int* in_sizes, int n_in,
                              void* d_out, int out_size)
{
    const float* X    = (const float*)d_in[0];
    const unsigned int* mask = (const unsigned int*)d_in[1];  // bool -> 4-byte: nonzero == masked
    const float* W_Q  = (const float*)d_in[2];
    const float* W_K  = (const float*)d_in[3];
    const float* W_V  = (const float*)d_in[4];
    const float* W_O  = (const float*)d_in[5];
    const float* gamma = (const float*)d_in[6];
    const float* beta  = (const float*)d_in[7];

    float *Qp, *Kp, *Vp, *Cp, *Yp, *Sp;
    cudaGetSymbolAddress((void**)&Qp, g_Q);
    cudaGetSymbolAddress((void**)&Kp, g_K);
    cudaGetSymbolAddress((void**)&Vp, g_V);
    cudaGetSymbolAddress((void**)&Cp, g_CTX);
    cudaGetSymbolAddress((void**)&Yp, g_Y);
    cudaGetSymbolAddress((void**)&Sp, g_S);

    const size_t LN_ELEMS   = (size_t)NROWS * DMODEL;                 // 8388608
    const size_t ATTN_ELEMS = (size_t)NBATCH * NHEADS * LSEQ * LSEQ;  // 134217728

    float* out_ln;
    float* attn_dst;
    if ((size_t)out_size >= LN_ELEMS + ATTN_ELEMS) {
        out_ln = (float*)d_out;
        attn_dst = (float*)d_out + LN_ELEMS;
    } else if ((size_t)out_size == ATTN_ELEMS) {
        attn_dst = (float*)d_out;
        out_ln = Yp;
    } else {
        out_ln = (float*)d_out;
        attn_dst = Sp;
    }

    dim3 thr(256);
    mma_nn_kernel<<<dim3(8, 64), thr>>>(X, W_Q, Qp, nullptr, DMODEL);
    mma_nn_kernel<<<dim3(8, 64), thr>>>(X, W_K, Kp, nullptr, DMODEL);
    mma_nn_kernel<<<dim3(8, 64), thr>>>(X, W_V, Vp, nullptr, DMODEL);
    mma_scores_kernel<<<dim3(8, 8, NBATCH * NHEADS), thr>>>(Qp, Kp, attn_dst, mask);
    softmax_kernel<<<dim3(NBATCH * NHEADS * LSEQ), thr>>>(attn_dst);
    mma_av_kernel<<<dim3(1, 8, NBATCH * NHEADS), thr>>>(attn_dst, Vp, Cp);
    mma_nn_kernel<<<dim3(8, 64), thr>>>(Cp, W_O, Yp, X, DMODEL);
    ln_kernel<<<dim3(NROWS), thr>>>(Yp, out_ln, gamma, beta);
}